// round 1
// baseline (speedup 1.0000x reference)
#include <cuda_runtime.h>
#include <cuda_bf16.h>

#define N_NODES 50000
#define N_EDGES 800000
#define N_GRAPHS 1024
#define DIM 300
#define N_LAYERS 5
#define FEAT 256
#define EPS 1e-5f

// ---------------- scratch (static device globals; no allocation) -------------
__device__ float g_h[N_NODES * DIM];     // layer input  (60 MB)
__device__ float g_hw[N_NODES * DIM];    // h @ W[l]     (60 MB)
__device__ float g_agg[N_NODES * DIM];   // accumulation (60 MB)
__device__ float g_stats[2 * DIM];       // col sum, col sumsq
__device__ float g_pool[N_GRAPHS * DIM];
__device__ float g_cnt[N_GRAPHS];
__device__ float g_hg[N_GRAPHS * DIM];
__device__ float g_hid[N_GRAPHS * FEAT];

// ---------------- node embedding --------------------------------------------
__global__ void embed_kernel(const int* __restrict__ x,
                             const float* __restrict__ emb1,
                             const float* __restrict__ emb2) {
    int i = blockIdx.x * blockDim.x + threadIdx.x;
    if (i >= N_NODES * DIM) return;
    int n = i / DIM, d = i - n * DIM;
    int a = x[2 * n], c = x[2 * n + 1];
    g_h[i] = emb1[a * DIM + d] + emb2[c * DIM + d];
}

// ---------------- main layer GEMM: hw = h @ W[l]; agg = hw + b + selfE -------
#define BM 128
#define BN 64
#define BK 8
#define TM 8
#define TN 4

__global__ __launch_bounds__(256)
void gemm_layer(const float* __restrict__ Wl,   // [DIM, DIM] row-major
                const float* __restrict__ bl,   // [DIM]
                const float* __restrict__ e1,   // [L,5,1]
                const float* __restrict__ e2,   // [L,3,1]
                int l) {
    __shared__ float As[BK][BM];
    __shared__ float Bs[BK][BN];
    int tid = threadIdx.x;
    int tx = tid & 15;   // N dir (16 * TN = 64)
    int ty = tid >> 4;   // M dir (16 * TM = 128)
    int m0 = blockIdx.y * BM;
    int n0 = blockIdx.x * BN;

    float acc[TM][TN];
#pragma unroll
    for (int i = 0; i < TM; i++)
#pragma unroll
        for (int j = 0; j < TN; j++) acc[i][j] = 0.f;

    int ar = tid >> 1;           // 0..127
    int ak = (tid & 1) * 4;      // 0 or 4
    int bk = tid >> 5;           // 0..7
    int bn = (tid & 31) * 2;     // 0..62

    for (int k0 = 0; k0 < DIM; k0 += BK) {
        int gm = m0 + ar;
#pragma unroll
        for (int j = 0; j < 4; j++) {
            int gk = k0 + ak + j;
            float v = 0.f;
            if (gm < N_NODES && gk < DIM) v = g_h[(long)gm * DIM + gk];
            As[ak + j][ar] = v;
        }
#pragma unroll
        for (int j = 0; j < 2; j++) {
            int gn = n0 + bn + j;
            int gk = k0 + bk;
            float v = 0.f;
            if (gk < DIM && gn < DIM) v = Wl[gk * DIM + gn];
            Bs[bk][bn + j] = v;
        }
        __syncthreads();
#pragma unroll
        for (int kk = 0; kk < BK; kk++) {
            float a[TM], bb[TN];
#pragma unroll
            for (int i = 0; i < TM; i++) a[i] = As[kk][ty * TM + i];
#pragma unroll
            for (int j = 0; j < TN; j++) bb[j] = Bs[kk][tx * TN + j];
#pragma unroll
            for (int i = 0; i < TM; i++)
#pragma unroll
                for (int j = 0; j < TN; j++) acc[i][j] += a[i] * bb[j];
        }
        __syncthreads();
    }

    float selfE = e1[l * 5 + 4] + e2[l * 3 + 0];
#pragma unroll
    for (int i = 0; i < TM; i++) {
        int m = m0 + ty * TM + i;
        if (m >= N_NODES) continue;
#pragma unroll
        for (int j = 0; j < TN; j++) {
            int n = n0 + tx * TN + j;
            if (n >= DIM) continue;
            float v = acc[i][j];
            long idx = (long)m * DIM + n;
            g_hw[idx] = v;
            g_agg[idx] = v + bl[n] + selfE;
        }
    }
}

// ---------------- edge scatter: agg[col] += hw[row] + eemb -------------------
#define EDGE_CHUNKS 75  // 300 / 4

__global__ void scatter_kernel(const int* __restrict__ ei,
                               const int* __restrict__ ea,
                               const float* __restrict__ e1,
                               const float* __restrict__ e2,
                               int l) {
    long t = (long)blockIdx.x * blockDim.x + threadIdx.x;
    if (t >= (long)N_EDGES * EDGE_CHUNKS) return;
    int e = (int)(t / EDGE_CHUNKS);
    int j = (int)(t - (long)e * EDGE_CHUNKS) * 4;
    int row = ei[e];
    int col = ei[N_EDGES + e];
    float em = e1[l * 5 + ea[2 * e]] + e2[l * 3 + ea[2 * e + 1]];
    const float4 hv = *(const float4*)&g_hw[(long)row * DIM + j];
    float* dst = &g_agg[(long)col * DIM + j];
    atomicAdd(dst + 0, hv.x + em);
    atomicAdd(dst + 1, hv.y + em);
    atomicAdd(dst + 2, hv.z + em);
    atomicAdd(dst + 3, hv.w + em);
}

// ---------------- batch norm stats + apply -----------------------------------
__global__ void zero_stats() {
    int i = blockIdx.x * blockDim.x + threadIdx.x;
    if (i < 2 * DIM) g_stats[i] = 0.f;
}

#define STAT_ROWS 50
__global__ void stats_kernel() {
    int tid = threadIdx.x;            // 128 threads
    int r0 = blockIdx.x * STAT_ROWS;  // 1000 blocks
    int c0 = tid, c1 = tid + 128, c2 = tid + 256;
    float s0 = 0, q0 = 0, s1 = 0, q1 = 0, s2 = 0, q2 = 0;
    int rend = r0 + STAT_ROWS;
    if (rend > N_NODES) rend = N_NODES;
    for (int r = r0; r < rend; r++) {
        const float* p = &g_agg[(long)r * DIM];
        float v0 = p[c0]; s0 += v0; q0 += v0 * v0;
        float v1 = p[c1]; s1 += v1; q1 += v1 * v1;
        if (c2 < DIM) { float v2 = p[c2]; s2 += v2; q2 += v2 * v2; }
    }
    atomicAdd(&g_stats[c0], s0);
    atomicAdd(&g_stats[DIM + c0], q0);
    atomicAdd(&g_stats[c1], s1);
    atomicAdd(&g_stats[DIM + c1], q1);
    if (c2 < DIM) {
        atomicAdd(&g_stats[c2], s2);
        atomicAdd(&g_stats[DIM + c2], q2);
    }
}

__global__ void bn_kernel(const float* __restrict__ gamma,
                          const float* __restrict__ beta,
                          int l, int do_relu) {
    int i = blockIdx.x * blockDim.x + threadIdx.x;
    if (i >= N_NODES * DIM) return;
    int d = i % DIM;
    const float inv_n = 1.0f / (float)N_NODES;
    float mu = g_stats[d] * inv_n;
    float var = g_stats[DIM + d] * inv_n - mu * mu;
    float v = (g_agg[i] - mu) * rsqrtf(var + EPS) * gamma[l * DIM + d] + beta[l * DIM + d];
    if (do_relu) v = fmaxf(v, 0.f);
    g_h[i] = v;
}

// ---------------- global mean pool -------------------------------------------
__global__ void zero_pool() {
    int i = blockIdx.x * blockDim.x + threadIdx.x;
    if (i < N_GRAPHS * DIM) g_pool[i] = 0.f;
    if (i < N_GRAPHS) g_cnt[i] = 0.f;
}

__global__ void pool_kernel(const int* __restrict__ batch) {
    long t = (long)blockIdx.x * blockDim.x + threadIdx.x;
    if (t >= (long)N_NODES * EDGE_CHUNKS) return;
    int n = (int)(t / EDGE_CHUNKS);
    int j = (int)(t - (long)n * EDGE_CHUNKS) * 4;
    int g = batch[n];
    const float4 hv = *(const float4*)&g_h[(long)n * DIM + j];
    float* dst = &g_pool[(long)g * DIM + j];
    atomicAdd(dst + 0, hv.x);
    atomicAdd(dst + 1, hv.y);
    atomicAdd(dst + 2, hv.z);
    atomicAdd(dst + 3, hv.w);
    if (j == 0) atomicAdd(&g_cnt[g], 1.0f);
}

__global__ void div_kernel() {
    int i = blockIdx.x * blockDim.x + threadIdx.x;
    if (i >= N_GRAPHS * DIM) return;
    g_hg[i] = g_pool[i] / fmaxf(g_cnt[i / DIM], 1.0f);
}

// ---------------- head MLPs --------------------------------------------------
__global__ void gemm_feat(const float* __restrict__ fw,  // [DIM, FEAT]
                          const float* __restrict__ fb,
                          float* __restrict__ hfeat) {
    __shared__ float sh[DIM];
    int g = blockIdx.x;
    int t = threadIdx.x;  // 256
    for (int k = t; k < DIM; k += FEAT) sh[k] = g_hg[g * DIM + k];
    __syncthreads();
    float acc = fb[t];
    for (int k = 0; k < DIM; k++) acc += sh[k] * fw[k * FEAT + t];
    hfeat[g * FEAT + t] = acc;
}

__global__ void gemm_mlp1(const float* __restrict__ hfeat,
                          const float* __restrict__ w1,
                          const float* __restrict__ b1) {
    __shared__ float sh[FEAT];
    int g = blockIdx.x;
    int t = threadIdx.x;  // 256
    sh[t] = hfeat[g * FEAT + t];
    __syncthreads();
    float acc = b1[t];
    for (int k = 0; k < FEAT; k++) acc += sh[k] * w1[k * FEAT + t];
    g_hid[g * FEAT + t] = fmaxf(acc, 0.f);
}

__global__ void gemm_mlp2(const float* __restrict__ w2,   // [FEAT, FEAT/2]
                          const float* __restrict__ b2,
                          float* __restrict__ out) {
    __shared__ float sh[FEAT];
    int g = blockIdx.x;
    int t = threadIdx.x;  // 128
    sh[t] = g_hid[g * FEAT + t];
    sh[t + 128] = g_hid[g * FEAT + t + 128];
    __syncthreads();
    float acc = b2[t];
    for (int k = 0; k < FEAT; k++) acc += sh[k] * w2[k * 128 + t];
    out[g * 128 + t] = acc;
}

// ---------------- launch -----------------------------------------------------
extern "C" void kernel_launch(void* const* d_in, const int* in_sizes, int n_in,
                              void* d_out, int out_size) {
    const int*   x     = (const int*)d_in[0];
    const int*   ei    = (const int*)d_in[1];
    const int*   ea    = (const int*)d_in[2];
    const int*   batch = (const int*)d_in[3];
    const float* emb1  = (const float*)d_in[4];
    const float* emb2  = (const float*)d_in[5];
    const float* W     = (const float*)d_in[6];
    const float* b     = (const float*)d_in[7];
    const float* e1    = (const float*)d_in[8];
    const float* e2    = (const float*)d_in[9];
    const float* gamma = (const float*)d_in[10];
    const float* beta  = (const float*)d_in[11];
    const float* fw    = (const float*)d_in[12];
    const float* fb    = (const float*)d_in[13];
    const float* w1    = (const float*)d_in[14];
    const float* b1    = (const float*)d_in[15];
    const float* w2    = (const float*)d_in[16];
    const float* b2    = (const float*)d_in[17];

    float* hfeat_out = (float*)d_out;                       // [G, FEAT]
    float* final_out = (float*)d_out + N_GRAPHS * FEAT;     // [G, FEAT/2]

    embed_kernel<<<(N_NODES * DIM + 255) / 256, 256>>>(x, emb1, emb2);

    dim3 ggrid((DIM + BN - 1) / BN, (N_NODES + BM - 1) / BM);
    long sc_threads = (long)N_EDGES * EDGE_CHUNKS;
    unsigned sc_blocks = (unsigned)((sc_threads + 255) / 256);

    for (int l = 0; l < N_LAYERS; l++) {
        gemm_layer<<<ggrid, 256>>>(W + (long)l * DIM * DIM, b + l * DIM, e1, e2, l);
        scatter_kernel<<<sc_blocks, 256>>>(ei, ea, e1, e2, l);
        zero_stats<<<3, 256>>>();
        stats_kernel<<<N_NODES / STAT_ROWS, 128>>>();
        bn_kernel<<<(N_NODES * DIM + 255) / 256, 256>>>(gamma, beta, l, l < N_LAYERS - 1);
    }

    zero_pool<<<(N_GRAPHS * DIM + 255) / 256, 256>>>();
    long pl_threads = (long)N_NODES * EDGE_CHUNKS;
    pool_kernel<<<(unsigned)((pl_threads + 255) / 256), 256>>>(batch);
    div_kernel<<<(N_GRAPHS * DIM + 255) / 256, 256>>>();

    gemm_feat<<<N_GRAPHS, FEAT>>>(fw, fb, hfeat_out);
    gemm_mlp1<<<N_GRAPHS, FEAT>>>(hfeat_out, w1, b1);
    gemm_mlp2<<<N_GRAPHS, 128>>>(w2, b2, final_out);
}

// round 2
// speedup vs baseline: 1.2253x; 1.2253x over previous
#include <cuda_runtime.h>
#include <cuda_bf16.h>

#define N_NODES 50000
#define N_EDGES 800000
#define N_GRAPHS 1024
#define DIM 300
#define N_LAYERS 5
#define FEAT 256
#define EPS 1e-5f

// ---------------- scratch (static device globals; no allocation) -------------
__device__ float g_h[N_NODES * DIM];     // layer input  (60 MB)
__device__ float g_hw[N_NODES * DIM];    // h @ W[l]     (60 MB)
__device__ float g_agg[N_NODES * DIM];   // accumulation (60 MB)
__device__ float g_stats[N_LAYERS * 2 * DIM];  // per-layer col sum, sumsq
__device__ float g_pool[N_GRAPHS * DIM];
__device__ float g_cnt[N_GRAPHS];
__device__ float g_hg[N_GRAPHS * DIM];
__device__ float g_hid[N_GRAPHS * FEAT];

// ---------------- node embedding + zero per-layer stats ----------------------
__global__ void embed_kernel(const int* __restrict__ x,
                             const float* __restrict__ emb1,
                             const float* __restrict__ emb2) {
    int i = blockIdx.x * blockDim.x + threadIdx.x;
    if (i < N_LAYERS * 2 * DIM) g_stats[i] = 0.f;
    if (i >= N_NODES * DIM) return;
    int n = i / DIM, d = i - n * DIM;
    int a = x[2 * n], c = x[2 * n + 1];
    g_h[i] = emb1[a * DIM + d] + emb2[c * DIM + d];
}

// ---------------- tf32 tensor-core GEMM: hw = h @ W[l]; agg = hw + b + selfE -
__device__ __forceinline__ unsigned f2tf32(float x) {
    unsigned u;
    asm("cvt.rna.tf32.f32 %0, %1;" : "=r"(u) : "f"(x));
    return u;
}

#define MMA_TF32(cc, A0, A1, A2, A3, B0, B1)                                   \
    asm volatile(                                                              \
        "mma.sync.aligned.m16n8k8.row.col.f32.tf32.tf32.f32 "                  \
        "{%0,%1,%2,%3},{%4,%5,%6,%7},{%8,%9},{%0,%1,%2,%3};"                   \
        : "+f"(cc[0]), "+f"(cc[1]), "+f"(cc[2]), "+f"(cc[3])                   \
        : "r"(A0), "r"(A1), "r"(A2), "r"(A3), "r"(B0), "r"(B1));

#define NKT 19  // ceil(300/16)

__global__ __launch_bounds__(256)
void gemm_layer_tc(const float* __restrict__ Wl,   // [DIM, DIM] row-major
                   const float* __restrict__ bl,   // [DIM]
                   const float* __restrict__ e1,   // [L,5,1]
                   const float* __restrict__ e2,   // [L,3,1]
                   int l) {
    __shared__ unsigned As[2][16][136];  // [k][m], stride 136 -> conflict-free
    __shared__ unsigned Bs[2][16][72];   // [k][n], stride 72  -> conflict-free

    const int tid = threadIdx.x;
    const int lane = tid & 31;
    const int warp = tid >> 5;
    const int g = lane >> 2;      // 0..7
    const int tg = lane & 3;      // 0..3
    const int wm = warp >> 1;     // 0..3  (m dir)
    const int wn = warp & 1;      // 0..1  (n dir)
    const int m0 = blockIdx.y * 128;
    const int n0 = blockIdx.x * 64;

    float c[2][4][4];
#pragma unroll
    for (int im = 0; im < 2; im++)
#pragma unroll
        for (int in = 0; in < 4; in++)
#pragma unroll
            for (int j = 0; j < 4; j++) c[im][in][j] = 0.f;

    // global-load assignments
    const int a_m = tid >> 1;          // 0..127
    const int a_k = (tid & 1) * 8;     // 0 or 8
    const int b_k = tid >> 4;          // 0..15
    const int b_n = (tid & 15) * 4;    // 0..60
    const int gm = m0 + a_m;

    float ar[8], br[4];

    // ---- prologue: load tile 0 ----
    {
        int gk = a_k;  // kt=0
        if (gm < N_NODES) {
            const float4 v0 = *(const float4*)&g_h[gm * DIM + gk];
            const float4 v1 = *(const float4*)&g_h[gm * DIM + gk + 4];
            ar[0] = v0.x; ar[1] = v0.y; ar[2] = v0.z; ar[3] = v0.w;
            ar[4] = v1.x; ar[5] = v1.y; ar[6] = v1.z; ar[7] = v1.w;
        } else {
#pragma unroll
            for (int j = 0; j < 8; j++) ar[j] = 0.f;
        }
        int gn = n0 + b_n;
        if (gn + 3 < DIM) {
            const float4 v = *(const float4*)&Wl[b_k * DIM + gn];
            br[0] = v.x; br[1] = v.y; br[2] = v.z; br[3] = v.w;
        } else {
#pragma unroll
            for (int j = 0; j < 4; j++)
                br[j] = (gn + j < DIM) ? Wl[b_k * DIM + gn + j] : 0.f;
        }
#pragma unroll
        for (int j = 0; j < 8; j++) As[0][a_k + j][a_m] = f2tf32(ar[j]);
#pragma unroll
        for (int j = 0; j < 4; j++) Bs[0][b_k][b_n + j] = f2tf32(br[j]);
    }
    __syncthreads();

#pragma unroll 1
    for (int kt = 0; kt < NKT; kt++) {
        const int buf = kt & 1;
        // ---- prefetch next tile into registers ----
        if (kt < NKT - 1) {
            int gk = (kt + 1) * 16 + a_k;
            if (gm < N_NODES && gk + 7 < DIM) {
                const float4 v0 = *(const float4*)&g_h[gm * DIM + gk];
                const float4 v1 = *(const float4*)&g_h[gm * DIM + gk + 4];
                ar[0] = v0.x; ar[1] = v0.y; ar[2] = v0.z; ar[3] = v0.w;
                ar[4] = v1.x; ar[5] = v1.y; ar[6] = v1.z; ar[7] = v1.w;
            } else {
#pragma unroll
                for (int j = 0; j < 8; j++)
                    ar[j] = (gm < N_NODES && gk + j < DIM)
                                ? g_h[gm * DIM + gk + j] : 0.f;
            }
            int gk2 = (kt + 1) * 16 + b_k;
            int gn = n0 + b_n;
            if (gk2 < DIM && gn + 3 < DIM) {
                const float4 v = *(const float4*)&Wl[gk2 * DIM + gn];
                br[0] = v.x; br[1] = v.y; br[2] = v.z; br[3] = v.w;
            } else {
#pragma unroll
                for (int j = 0; j < 4; j++)
                    br[j] = (gk2 < DIM && gn + j < DIM)
                                ? Wl[gk2 * DIM + gn + j] : 0.f;
            }
        }

        // ---- compute: two k8 steps ----
#pragma unroll
        for (int kb = 0; kb < 16; kb += 8) {
            unsigned a0[2], a1[2], a2[2], a3[2];
#pragma unroll
            for (int im = 0; im < 2; im++) {
                int mo = wm * 32 + im * 16;
                a0[im] = As[buf][kb + tg][mo + g];
                a1[im] = As[buf][kb + tg][mo + g + 8];
                a2[im] = As[buf][kb + tg + 4][mo + g];
                a3[im] = As[buf][kb + tg + 4][mo + g + 8];
            }
            unsigned b0[4], b1[4];
#pragma unroll
            for (int in = 0; in < 4; in++) {
                int no = wn * 32 + in * 8;
                b0[in] = Bs[buf][kb + tg][no + g];
                b1[in] = Bs[buf][kb + tg + 4][no + g];
            }
#pragma unroll
            for (int im = 0; im < 2; im++)
#pragma unroll
                for (int in = 0; in < 4; in++)
                    MMA_TF32(c[im][in], a0[im], a1[im], a2[im], a3[im],
                             b0[in], b1[in]);
        }

        // ---- stage prefetched regs into the other buffer ----
        if (kt < NKT - 1) {
            const int nb = buf ^ 1;
#pragma unroll
            for (int j = 0; j < 8; j++) As[nb][a_k + j][a_m] = f2tf32(ar[j]);
#pragma unroll
            for (int j = 0; j < 4; j++) Bs[nb][b_k][b_n + j] = f2tf32(br[j]);
        }
        __syncthreads();
    }

    // ---- epilogue ----
    const float selfE = e1[l * 5 + 4] + e2[l * 3 + 0];
#pragma unroll
    for (int in = 0; in < 4; in++) {
        int ncol = n0 + wn * 32 + in * 8 + 2 * tg;
        if (ncol >= DIM) continue;
        float add0 = bl[ncol] + selfE;
        float add1 = bl[ncol + 1] + selfE;
#pragma unroll
        for (int im = 0; im < 2; im++) {
            int r0 = m0 + wm * 32 + im * 16 + g;
            if (r0 < N_NODES) {
                int idx = r0 * DIM + ncol;
                *(float2*)&g_hw[idx] = make_float2(c[im][in][0], c[im][in][1]);
                *(float2*)&g_agg[idx] =
                    make_float2(c[im][in][0] + add0, c[im][in][1] + add1);
            }
            int r1 = r0 + 8;
            if (r1 < N_NODES) {
                int idx = r1 * DIM + ncol;
                *(float2*)&g_hw[idx] = make_float2(c[im][in][2], c[im][in][3]);
                *(float2*)&g_agg[idx] =
                    make_float2(c[im][in][2] + add0, c[im][in][3] + add1);
            }
        }
    }
}

// ---------------- edge scatter: agg[col] += hw[row] + eemb -------------------
#define EDGE_CHUNKS 75  // 300 / 4

__global__ void scatter_kernel(const int* __restrict__ ei,
                               const int* __restrict__ ea,
                               const float* __restrict__ e1,
                               const float* __restrict__ e2,
                               int l) {
    long t = (long)blockIdx.x * blockDim.x + threadIdx.x;
    if (t >= (long)N_EDGES * EDGE_CHUNKS) return;
    int e = (int)(t / EDGE_CHUNKS);
    int j = (int)(t - (long)e * EDGE_CHUNKS) * 4;
    int row = ei[e];
    int col = ei[N_EDGES + e];
    float em = e1[l * 5 + ea[2 * e]] + e2[l * 3 + ea[2 * e + 1]];
    const float4 hv = *(const float4*)&g_hw[(long)row * DIM + j];
    float* dst = &g_agg[(long)col * DIM + j];
    atomicAdd(dst + 0, hv.x + em);
    atomicAdd(dst + 1, hv.y + em);
    atomicAdd(dst + 2, hv.z + em);
    atomicAdd(dst + 3, hv.w + em);
}

// ---------------- batch norm stats + apply -----------------------------------
#define STAT_ROWS 50
__global__ void stats_kernel(int l) {
    int tid = threadIdx.x;            // 128 threads
    int r0 = blockIdx.x * STAT_ROWS;  // 1000 blocks
    float* st = &g_stats[l * 2 * DIM];
    int c0 = tid, c1 = tid + 128, c2 = tid + 256;
    float s0 = 0, q0 = 0, s1 = 0, q1 = 0, s2 = 0, q2 = 0;
    int rend = r0 + STAT_ROWS;
    if (rend > N_NODES) rend = N_NODES;
    for (int r = r0; r < rend; r++) {
        const float* p = &g_agg[(long)r * DIM];
        float v0 = p[c0]; s0 += v0; q0 += v0 * v0;
        float v1 = p[c1]; s1 += v1; q1 += v1 * v1;
        if (c2 < DIM) { float v2 = p[c2]; s2 += v2; q2 += v2 * v2; }
    }
    atomicAdd(&st[c0], s0);
    atomicAdd(&st[DIM + c0], q0);
    atomicAdd(&st[c1], s1);
    atomicAdd(&st[DIM + c1], q1);
    if (c2 < DIM) {
        atomicAdd(&st[c2], s2);
        atomicAdd(&st[DIM + c2], q2);
    }
}

__global__ void bn_kernel(const float* __restrict__ gamma,
                          const float* __restrict__ beta,
                          int l, int do_relu) {
    int i = blockIdx.x * blockDim.x + threadIdx.x;
    if (i >= N_NODES * DIM) return;
    int d = i % DIM;
    const float* st = &g_stats[l * 2 * DIM];
    const float inv_n = 1.0f / (float)N_NODES;
    float mu = st[d] * inv_n;
    float var = st[DIM + d] * inv_n - mu * mu;
    float v = (g_agg[i] - mu) * rsqrtf(var + EPS) * gamma[l * DIM + d] + beta[l * DIM + d];
    if (do_relu) v = fmaxf(v, 0.f);
    g_h[i] = v;
}

// ---------------- global mean pool -------------------------------------------
__global__ void zero_pool() {
    int i = blockIdx.x * blockDim.x + threadIdx.x;
    if (i < N_GRAPHS * DIM) g_pool[i] = 0.f;
    if (i < N_GRAPHS) g_cnt[i] = 0.f;
}

__global__ void pool_kernel(const int* __restrict__ batch) {
    long t = (long)blockIdx.x * blockDim.x + threadIdx.x;
    if (t >= (long)N_NODES * EDGE_CHUNKS) return;
    int n = (int)(t / EDGE_CHUNKS);
    int j = (int)(t - (long)n * EDGE_CHUNKS) * 4;
    int g = batch[n];
    const float4 hv = *(const float4*)&g_h[(long)n * DIM + j];
    float* dst = &g_pool[(long)g * DIM + j];
    atomicAdd(dst + 0, hv.x);
    atomicAdd(dst + 1, hv.y);
    atomicAdd(dst + 2, hv.z);
    atomicAdd(dst + 3, hv.w);
    if (j == 0) atomicAdd(&g_cnt[g], 1.0f);
}

__global__ void div_kernel() {
    int i = blockIdx.x * blockDim.x + threadIdx.x;
    if (i >= N_GRAPHS * DIM) return;
    g_hg[i] = g_pool[i] / fmaxf(g_cnt[i / DIM], 1.0f);
}

// ---------------- head MLPs --------------------------------------------------
__global__ void gemm_feat(const float* __restrict__ fw,  // [DIM, FEAT]
                          const float* __restrict__ fb,
                          float* __restrict__ hfeat) {
    __shared__ float sh[DIM];
    int g = blockIdx.x;
    int t = threadIdx.x;  // 256
    for (int k = t; k < DIM; k += FEAT) sh[k] = g_hg[g * DIM + k];
    __syncthreads();
    float acc = fb[t];
    for (int k = 0; k < DIM; k++) acc += sh[k] * fw[k * FEAT + t];
    hfeat[g * FEAT + t] = acc;
}

__global__ void gemm_mlp1(const float* __restrict__ hfeat,
                          const float* __restrict__ w1,
                          const float* __restrict__ b1) {
    __shared__ float sh[FEAT];
    int g = blockIdx.x;
    int t = threadIdx.x;  // 256
    sh[t] = hfeat[g * FEAT + t];
    __syncthreads();
    float acc = b1[t];
    for (int k = 0; k < FEAT; k++) acc += sh[k] * w1[k * FEAT + t];
    g_hid[g * FEAT + t] = fmaxf(acc, 0.f);
}

__global__ void gemm_mlp2(const float* __restrict__ w2,   // [FEAT, FEAT/2]
                          const float* __restrict__ b2,
                          float* __restrict__ out) {
    __shared__ float sh[FEAT];
    int g = blockIdx.x;
    int t = threadIdx.x;  // 128
    sh[t] = g_hid[g * FEAT + t];
    sh[t + 128] = g_hid[g * FEAT + t + 128];
    __syncthreads();
    float acc = b2[t];
    for (int k = 0; k < FEAT; k++) acc += sh[k] * w2[k * 128 + t];
    out[g * 128 + t] = acc;
}

// ---------------- launch -----------------------------------------------------
extern "C" void kernel_launch(void* const* d_in, const int* in_sizes, int n_in,
                              void* d_out, int out_size) {
    const int*   x     = (const int*)d_in[0];
    const int*   ei    = (const int*)d_in[1];
    const int*   ea    = (const int*)d_in[2];
    const int*   batch = (const int*)d_in[3];
    const float* emb1  = (const float*)d_in[4];
    const float* emb2  = (const float*)d_in[5];
    const float* W     = (const float*)d_in[6];
    const float* b     = (const float*)d_in[7];
    const float* e1    = (const float*)d_in[8];
    const float* e2    = (const float*)d_in[9];
    const float* gamma = (const float*)d_in[10];
    const float* beta  = (const float*)d_in[11];
    const float* fw    = (const float*)d_in[12];
    const float* fb    = (const float*)d_in[13];
    const float* w1    = (const float*)d_in[14];
    const float* b1    = (const float*)d_in[15];
    const float* w2    = (const float*)d_in[16];
    const float* b2    = (const float*)d_in[17];

    float* hfeat_out = (float*)d_out;                       // [G, FEAT]
    float* final_out = (float*)d_out + N_GRAPHS * FEAT;     // [G, FEAT/2]

    embed_kernel<<<(N_NODES * DIM + 255) / 256, 256>>>(x, emb1, emb2);

    dim3 ggrid((DIM + 63) / 64, (N_NODES + 127) / 128);
    long sc_threads = (long)N_EDGES * EDGE_CHUNKS;
    unsigned sc_blocks = (unsigned)((sc_threads + 255) / 256);

    for (int l = 0; l < N_LAYERS; l++) {
        gemm_layer_tc<<<ggrid, 256>>>(W + (long)l * DIM * DIM, b + l * DIM, e1, e2, l);
        scatter_kernel<<<sc_blocks, 256>>>(ei, ea, e1, e2, l);
        stats_kernel<<<N_NODES / STAT_ROWS, 128>>>(l);
        bn_kernel<<<(N_NODES * DIM + 255) / 256, 256>>>(gamma, beta, l, l < N_LAYERS - 1);
    }

    zero_pool<<<(N_GRAPHS * DIM + 255) / 256, 256>>>();
    long pl_threads = (long)N_NODES * EDGE_CHUNKS;
    pool_kernel<<<(unsigned)((pl_threads + 255) / 256), 256>>>(batch);
    div_kernel<<<(N_GRAPHS * DIM + 255) / 256, 256>>>();

    gemm_feat<<<N_GRAPHS, FEAT>>>(fw, fb, hfeat_out);
    gemm_mlp1<<<N_GRAPHS, FEAT>>>(hfeat_out, w1, b1);
    gemm_mlp2<<<N_GRAPHS, 128>>>(w2, b2, final_out);
}

// round 4
// speedup vs baseline: 2.4372x; 1.9891x over previous
#include <cuda_runtime.h>
#include <cuda_bf16.h>

#define N_NODES 50000
#define N_EDGES 800000
#define N_GRAPHS 1024
#define DIM 300
#define N_LAYERS 5
#define FEAT 256
#define EPS 1e-5f
#define NBLK_SCAN ((N_NODES + 255) / 256)   // 196

// ---------------- scratch (static device globals; no allocation) -------------
__device__ float g_h[N_NODES * DIM];     // layer input  (60 MB)
__device__ float g_hw[N_NODES * DIM];    // h @ W[l]     (60 MB)
__device__ float g_agg[N_NODES * DIM];   // accumulation (60 MB)
__device__ float g_stats[N_LAYERS * 2 * DIM];  // per-layer col sum, sumsq
__device__ float g_hg[N_GRAPHS * DIM];
__device__ float g_hid[N_GRAPHS * FEAT];
// CSR build
__device__ int g_deg[N_NODES];
__device__ int g_incl[N_NODES];
__device__ int g_bsum[NBLK_SCAN];
__device__ int g_boff[NBLK_SCAN];
__device__ int g_cursor[N_NODES];
__device__ int g_start[N_NODES + 1];
__device__ int g_csr[N_EDGES];           // row | (attr<<16)
__device__ int g_gstart[N_GRAPHS + 1];

// ---------------- node embedding + zero deg/stats ----------------------------
__global__ void embed_kernel(const int* __restrict__ x,
                             const float* __restrict__ emb1,
                             const float* __restrict__ emb2) {
    int i = blockIdx.x * blockDim.x + threadIdx.x;
    if (i < N_LAYERS * 2 * DIM) g_stats[i] = 0.f;
    if (i < N_NODES) g_deg[i] = 0;
    if (i >= N_NODES * DIM) return;
    int n = i / DIM, d = i - n * DIM;
    int a = x[2 * n], c = x[2 * n + 1];
    g_h[i] = emb1[a * DIM + d] + emb2[c * DIM + d];
}

// ---------------- CSR build ---------------------------------------------------
__global__ void hist_kernel(const int* __restrict__ ei) {
    int e = blockIdx.x * blockDim.x + threadIdx.x;
    if (e >= N_EDGES) return;
    atomicAdd(&g_deg[ei[N_EDGES + e]], 1);
}

__global__ void scan1_kernel() {   // per-256-chunk inclusive scan
    __shared__ int s[256];
    int tid = threadIdx.x;
    int i = blockIdx.x * 256 + tid;
    int v = (i < N_NODES) ? g_deg[i] : 0;
    s[tid] = v;
    __syncthreads();
#pragma unroll
    for (int off = 1; off < 256; off <<= 1) {
        int t = (tid >= off) ? s[tid - off] : 0;
        __syncthreads();
        s[tid] += t;
        __syncthreads();
    }
    if (i < N_NODES) g_incl[i] = s[tid];
    if (tid == 255) g_bsum[blockIdx.x] = s[255];
}

__global__ void scan2_kernel() {   // exclusive scan of block sums (1 block)
    __shared__ int s[256];
    int tid = threadIdx.x;
    s[tid] = (tid < NBLK_SCAN) ? g_bsum[tid] : 0;
    __syncthreads();
#pragma unroll
    for (int off = 1; off < 256; off <<= 1) {
        int t = (tid >= off) ? s[tid - off] : 0;
        __syncthreads();
        s[tid] += t;
        __syncthreads();
    }
    if (tid < NBLK_SCAN) g_boff[tid] = s[tid] - g_bsum[tid];  // exclusive
}

__global__ void scan3_kernel() {   // finalize starts, zero cursors
    int i = blockIdx.x * blockDim.x + threadIdx.x;
    if (i >= N_NODES) return;
    g_start[i + 1] = g_incl[i] + g_boff[i >> 8];
    g_cursor[i] = 0;
    if (i == 0) g_start[0] = 0;
}

__global__ void fill_kernel(const int* __restrict__ ei,
                            const int* __restrict__ ea) {
    int e = blockIdx.x * blockDim.x + threadIdx.x;
    if (e >= N_EDGES) return;
    int row = ei[e];
    int col = ei[N_EDGES + e];
    int attr = ea[2 * e] * 3 + ea[2 * e + 1];  // 0..8
    int pos = g_start[col] + atomicAdd(&g_cursor[col], 1);
    g_csr[pos] = row | (attr << 16);
}

// ---------------- 3xTF32 tensor-core GEMM: hw = h @ W[l] ---------------------
__device__ __forceinline__ unsigned f2tf32(float x) {
    unsigned u;
    asm("cvt.rna.tf32.f32 %0, %1;" : "=r"(u) : "f"(x));
    return u;
}

#define MMA_TF32(cc, A0, A1, A2, A3, B0, B1)                                   \
    asm volatile(                                                              \
        "mma.sync.aligned.m16n8k8.row.col.f32.tf32.tf32.f32 "                  \
        "{%0,%1,%2,%3},{%4,%5,%6,%7},{%8,%9},{%0,%1,%2,%3};"                   \
        : "+f"(cc[0]), "+f"(cc[1]), "+f"(cc[2]), "+f"(cc[3])                   \
        : "r"(A0), "r"(A1), "r"(A2), "r"(A3), "r"(B0), "r"(B1));

#define NKT 38  // ceil(300/8)

__global__ __launch_bounds__(256)
void gemm_layer_tc(const float* __restrict__ Wl) {  // [DIM, DIM] row-major
    __shared__ unsigned Ah[2][8][136], Al[2][8][136];  // [k][m]
    __shared__ unsigned Bh[2][8][72],  Bl[2][8][72];   // [k][n]

    const int tid = threadIdx.x;
    const int lane = tid & 31;
    const int warp = tid >> 5;
    const int g = lane >> 2;      // 0..7
    const int tg = lane & 3;      // 0..3
    const int wm = warp >> 1;     // 0..3  (m dir)
    const int wn = warp & 1;      // 0..1  (n dir)
    const int m0 = blockIdx.y * 128;
    const int n0 = blockIdx.x * 64;

    float c[2][4][4];
#pragma unroll
    for (int im = 0; im < 2; im++)
#pragma unroll
        for (int in = 0; in < 4; in++)
#pragma unroll
            for (int j = 0; j < 4; j++) c[im][in][j] = 0.f;

    const int a_m = tid >> 1;          // 0..127
    const int a_k = (tid & 1) * 4;     // 0 or 4
    const int b_k = tid >> 5;          // 0..7
    const int b_n = (tid & 31) * 2;    // 0..62
    const int gm = m0 + a_m;

    float ar[4], br[2];

    // ---- prologue: load tile 0 ----
    {
        if (gm < N_NODES) {
            const float4 v = *(const float4*)&g_h[gm * DIM + a_k];
            ar[0] = v.x; ar[1] = v.y; ar[2] = v.z; ar[3] = v.w;
        } else {
            ar[0] = ar[1] = ar[2] = ar[3] = 0.f;
        }
        int gn = n0 + b_n;
        if (gn + 1 < DIM) {
            const float2 v = *(const float2*)&Wl[b_k * DIM + gn];
            br[0] = v.x; br[1] = v.y;
        } else {
            br[0] = (gn < DIM) ? Wl[b_k * DIM + gn] : 0.f;
            br[1] = 0.f;
        }
#pragma unroll
        for (int j = 0; j < 4; j++) {
            unsigned hi = f2tf32(ar[j]);
            Ah[0][a_k + j][a_m] = hi;
            Al[0][a_k + j][a_m] = f2tf32(ar[j] - __uint_as_float(hi));
        }
#pragma unroll
        for (int j = 0; j < 2; j++) {
            unsigned hi = f2tf32(br[j]);
            Bh[0][b_k][b_n + j] = hi;
            Bl[0][b_k][b_n + j] = f2tf32(br[j] - __uint_as_float(hi));
        }
    }
    __syncthreads();

#pragma unroll 1
    for (int kt = 0; kt < NKT; kt++) {
        const int buf = kt & 1;
        // ---- prefetch next tile into registers ----
        if (kt < NKT - 1) {
            int gk = (kt + 1) * 8 + a_k;
            if (gm < N_NODES && gk + 3 < DIM) {
                const float4 v = *(const float4*)&g_h[gm * DIM + gk];
                ar[0] = v.x; ar[1] = v.y; ar[2] = v.z; ar[3] = v.w;
            } else {
#pragma unroll
                for (int j = 0; j < 4; j++)
                    ar[j] = (gm < N_NODES && gk + j < DIM)
                                ? g_h[gm * DIM + gk + j] : 0.f;
            }
            int gk2 = (kt + 1) * 8 + b_k;
            int gn = n0 + b_n;
            if (gk2 < DIM && gn + 1 < DIM) {
                const float2 v = *(const float2*)&Wl[gk2 * DIM + gn];
                br[0] = v.x; br[1] = v.y;
            } else {
#pragma unroll
                for (int j = 0; j < 2; j++)
                    br[j] = (gk2 < DIM && gn + j < DIM)
                                ? Wl[gk2 * DIM + gn + j] : 0.f;
            }
        }

        // ---- compute: one k8 step, 3xTF32 ----
        {
            unsigned ah0[2], ah1[2], ah2[2], ah3[2];
            unsigned al0[2], al1[2], al2[2], al3[2];
#pragma unroll
            for (int im = 0; im < 2; im++) {
                int mo = wm * 32 + im * 16;
                ah0[im] = Ah[buf][tg][mo + g];
                ah1[im] = Ah[buf][tg][mo + g + 8];
                ah2[im] = Ah[buf][tg + 4][mo + g];
                ah3[im] = Ah[buf][tg + 4][mo + g + 8];
                al0[im] = Al[buf][tg][mo + g];
                al1[im] = Al[buf][tg][mo + g + 8];
                al2[im] = Al[buf][tg + 4][mo + g];
                al3[im] = Al[buf][tg + 4][mo + g + 8];
            }
            unsigned bh0[4], bh1[4], bl0[4], bl1[4];
#pragma unroll
            for (int in = 0; in < 4; in++) {
                int no = wn * 32 + in * 8;
                bh0[in] = Bh[buf][tg][no + g];
                bh1[in] = Bh[buf][tg + 4][no + g];
                bl0[in] = Bl[buf][tg][no + g];
                bl1[in] = Bl[buf][tg + 4][no + g];
            }
#pragma unroll
            for (int im = 0; im < 2; im++)
#pragma unroll
                for (int in = 0; in < 4; in++) {
                    MMA_TF32(c[im][in], al0[im], al1[im], al2[im], al3[im],
                             bh0[in], bh1[in]);
                    MMA_TF32(c[im][in], ah0[im], ah1[im], ah2[im], ah3[im],
                             bl0[in], bl1[in]);
                    MMA_TF32(c[im][in], ah0[im], ah1[im], ah2[im], ah3[im],
                             bh0[in], bh1[in]);
                }
        }

        // ---- stage prefetched regs into the other buffer ----
        if (kt < NKT - 1) {
            const int nb = buf ^ 1;
#pragma unroll
            for (int j = 0; j < 4; j++) {
                unsigned hi = f2tf32(ar[j]);
                Ah[nb][a_k + j][a_m] = hi;
                Al[nb][a_k + j][a_m] = f2tf32(ar[j] - __uint_as_float(hi));
            }
#pragma unroll
            for (int j = 0; j < 2; j++) {
                unsigned hi = f2tf32(br[j]);
                Bh[nb][b_k][b_n + j] = hi;
                Bl[nb][b_k][b_n + j] = f2tf32(br[j] - __uint_as_float(hi));
            }
        }
        __syncthreads();
    }

    // ---- epilogue: write g_hw only ----
#pragma unroll
    for (int in = 0; in < 4; in++) {
        int ncol = n0 + wn * 32 + in * 8 + 2 * tg;
        if (ncol >= DIM) continue;
#pragma unroll
        for (int im = 0; im < 2; im++) {
            int r0 = m0 + wm * 32 + im * 16 + g;
            if (r0 < N_NODES)
                *(float2*)&g_hw[r0 * DIM + ncol] =
                    make_float2(c[im][in][0], c[im][in][1]);
            int r1 = r0 + 8;
            if (r1 < N_NODES)
                *(float2*)&g_hw[r1 * DIM + ncol] =
                    make_float2(c[im][in][2], c[im][in][3]);
        }
    }
}

// ---------------- CSR aggregation: agg[n] = sum_in(hw[row]+em) + hw[n]+b+sE --
__global__ __launch_bounds__(128)
void agg_kernel(const float* __restrict__ bl,
                const float* __restrict__ e1,
                const float* __restrict__ e2,
                int l) {
    __shared__ float s_em[9];
    __shared__ int s_pk[128];
    const int n = blockIdx.x;
    const int tid = threadIdx.x;
    if (tid < 9) s_em[tid] = e1[l * 5 + tid / 3] + e2[l * 3 + tid % 3];
    const float selfE = e1[l * 5 + 4] + e2[l * 3 + 0];
    __syncthreads();
    const int start = g_start[n], end = g_start[n + 1];
    const int d0 = tid, d1 = tid + 128, d2 = tid + 256;
    float a0 = 0.f, a1 = 0.f, a2 = 0.f;
    for (int base = start; base < end; base += 128) {
        int idx = base + tid;
        if (idx < end) s_pk[tid] = g_csr[idx];
        __syncthreads();
        int cnt = min(128, end - base);
        for (int i = 0; i < cnt; i++) {
            int pk = s_pk[i];
            const float* p = g_hw + (pk & 0xFFFF) * DIM;
            float em = s_em[pk >> 16];
            a0 += p[d0] + em;
            a1 += p[d1] + em;
            if (d2 < DIM) a2 += p[d2] + em;
        }
        __syncthreads();
    }
    const float* hp = g_hw + n * DIM;
    float* op = g_agg + n * DIM;
    op[d0] = a0 + hp[d0] + bl[d0] + selfE;
    op[d1] = a1 + hp[d1] + bl[d1] + selfE;
    if (d2 < DIM) op[d2] = a2 + hp[d2] + bl[d2] + selfE;
}

// ---------------- batch norm stats + apply -----------------------------------
#define STAT_ROWS 50
__global__ void stats_kernel(int l) {
    int tid = threadIdx.x;            // 128 threads
    int r0 = blockIdx.x * STAT_ROWS;  // 1000 blocks
    float* st = &g_stats[l * 2 * DIM];
    int c0 = tid, c1 = tid + 128, c2 = tid + 256;
    float s0 = 0, q0 = 0, s1 = 0, q1 = 0, s2 = 0, q2 = 0;
    int rend = r0 + STAT_ROWS;
    if (rend > N_NODES) rend = N_NODES;
    for (int r = r0; r < rend; r++) {
        const float* p = &g_agg[(long)r * DIM];
        float v0 = p[c0]; s0 += v0; q0 += v0 * v0;
        float v1 = p[c1]; s1 += v1; q1 += v1 * v1;
        if (c2 < DIM) { float v2 = p[c2]; s2 += v2; q2 += v2 * v2; }
    }
    atomicAdd(&st[c0], s0);
    atomicAdd(&st[DIM + c0], q0);
    atomicAdd(&st[c1], s1);
    atomicAdd(&st[DIM + c1], q1);
    if (c2 < DIM) {
        atomicAdd(&st[c2], s2);
        atomicAdd(&st[DIM + c2], q2);
    }
}

__global__ void bn_kernel(const float* __restrict__ gamma,
                          const float* __restrict__ beta,
                          int l, int do_relu) {
    int i = blockIdx.x * blockDim.x + threadIdx.x;
    if (i >= N_NODES * DIM) return;
    int d = i % DIM;
    const float* st = &g_stats[l * 2 * DIM];
    const float inv_n = 1.0f / (float)N_NODES;
    float mu = st[d] * inv_n;
    float var = st[DIM + d] * inv_n - mu * mu;
    float v = (g_agg[i] - mu) * rsqrtf(var + EPS) * gamma[l * DIM + d] + beta[l * DIM + d];
    if (do_relu) v = fmaxf(v, 0.f);
    g_h[i] = v;
}

// ---------------- pool (batch is sorted -> contiguous segments) --------------
__global__ void gbound_kernel(const int* __restrict__ batch) {
    int g = blockIdx.x * blockDim.x + threadIdx.x;
    if (g > N_GRAPHS) return;
    int lo = 0, hi = N_NODES;
    while (lo < hi) {
        int mid = (lo + hi) >> 1;
        if (batch[mid] < g) lo = mid + 1; else hi = mid;
    }
    g_gstart[g] = lo;
}

__global__ __launch_bounds__(128)
void pool_kernel() {
    const int g = blockIdx.x;
    const int tid = threadIdx.x;
    const int gs = g_gstart[g], ge = g_gstart[g + 1];
    const int d0 = tid, d1 = tid + 128, d2 = tid + 256;
    float a0 = 0.f, a1 = 0.f, a2 = 0.f;
    for (int r = gs; r < ge; r++) {
        const float* p = g_h + r * DIM;
        a0 += p[d0];
        a1 += p[d1];
        if (d2 < DIM) a2 += p[d2];
    }
    float inv = 1.0f / fmaxf((float)(ge - gs), 1.0f);
    float* op = g_hg + g * DIM;
    op[d0] = a0 * inv;
    op[d1] = a1 * inv;
    if (d2 < DIM) op[d2] = a2 * inv;
}

// ---------------- head MLPs --------------------------------------------------
__global__ void gemm_feat(const float* __restrict__ fw,  // [DIM, FEAT]
                          const float* __restrict__ fb,
                          float* __restrict__ hfeat) {
    __shared__ float sh[DIM];
    int g = blockIdx.x;
    int t = threadIdx.x;  // 256
    for (int k = t; k < DIM; k += FEAT) sh[k] = g_hg[g * DIM + k];
    __syncthreads();
    float acc = fb[t];
    for (int k = 0; k < DIM; k++) acc += sh[k] * fw[k * FEAT + t];
    hfeat[g * FEAT + t] = acc;
}

__global__ void gemm_mlp1(const float* __restrict__ hfeat,
                          const float* __restrict__ w1,
                          const float* __restrict__ b1) {
    __shared__ float sh[FEAT];
    int g = blockIdx.x;
    int t = threadIdx.x;  // 256
    sh[t] = hfeat[g * FEAT + t];
    __syncthreads();
    float acc = b1[t];
    for (int k = 0; k < FEAT; k++) acc += sh[k] * w1[k * FEAT + t];
    g_hid[g * FEAT + t] = fmaxf(acc, 0.f);
}

__global__ void gemm_mlp2(const float* __restrict__ w2,   // [FEAT, FEAT/2]
                          const float* __restrict__ b2,
                          float* __restrict__ out) {
    __shared__ float sh[FEAT];
    int g = blockIdx.x;
    int t = threadIdx.x;  // 128
    sh[t] = g_hid[g * FEAT + t];
    sh[t + 128] = g_hid[g * FEAT + t + 128];
    __syncthreads();
    float acc = b2[t];
    for (int k = 0; k < FEAT; k++) acc += sh[k] * w2[k * 128 + t];
    out[g * 128 + t] = acc;
}

// ---------------- launch -----------------------------------------------------
extern "C" void kernel_launch(void* const* d_in, const int* in_sizes, int n_in,
                              void* d_out, int out_size) {
    const int*   x     = (const int*)d_in[0];
    const int*   ei    = (const int*)d_in[1];
    const int*   ea    = (const int*)d_in[2];
    const int*   batch = (const int*)d_in[3];
    const float* emb1  = (const float*)d_in[4];
    const float* emb2  = (const float*)d_in[5];
    const float* W     = (const float*)d_in[6];
    const float* b     = (const float*)d_in[7];
    const float* e1    = (const float*)d_in[8];
    const float* e2    = (const float*)d_in[9];
    const float* gamma = (const float*)d_in[10];
    const float* beta  = (const float*)d_in[11];
    const float* fw    = (const float*)d_in[12];
    const float* fb    = (const float*)d_in[13];
    const float* w1    = (const float*)d_in[14];
    const float* b1    = (const float*)d_in[15];
    const float* w2    = (const float*)d_in[16];
    const float* b2    = (const float*)d_in[17];

    float* hfeat_out = (float*)d_out;                       // [G, FEAT]
    float* final_out = (float*)d_out + N_GRAPHS * FEAT;     // [G, FEAT/2]

    embed_kernel<<<(N_NODES * DIM + 255) / 256, 256>>>(x, emb1, emb2);

    // CSR build (once per launch)
    hist_kernel<<<(N_EDGES + 255) / 256, 256>>>(ei);
    scan1_kernel<<<NBLK_SCAN, 256>>>();
    scan2_kernel<<<1, 256>>>();
    scan3_kernel<<<(N_NODES + 255) / 256, 256>>>();
    fill_kernel<<<(N_EDGES + 255) / 256, 256>>>(ei, ea);

    dim3 ggrid((DIM + 63) / 64, (N_NODES + 127) / 128);
    for (int l = 0; l < N_LAYERS; l++) {
        gemm_layer_tc<<<ggrid, 256>>>(W + (long)l * DIM * DIM);
        agg_kernel<<<N_NODES, 128>>>(b + l * DIM, e1, e2, l);
        stats_kernel<<<N_NODES / STAT_ROWS, 128>>>(l);
        bn_kernel<<<(N_NODES * DIM + 255) / 256, 256>>>(gamma, beta, l, l < N_LAYERS - 1);
    }

    gbound_kernel<<<(N_GRAPHS + 256) / 256, 256>>>(batch);
    pool_kernel<<<N_GRAPHS, 128>>>();

    gemm_feat<<<N_GRAPHS, FEAT>>>(fw, fb, hfeat_out);
    gemm_mlp1<<<N_GRAPHS, FEAT>>>(hfeat_out, w1, b1);
    gemm_mlp2<<<N_GRAPHS, 128>>>(w2, b2, final_out);
}